// round 3
// baseline (speedup 1.0000x reference)
#include <cuda_runtime.h>

#define QPB 4          // queries per block
#define LN_EPS 1e-5f
#define Z_EPS  1e-5f

// Reduce 4 independent values (one per query) across 256 threads.
__device__ __forceinline__ void blockSum256x4(float v[QPB], float4* red) {
    const int tid = threadIdx.x;
    red[tid] = make_float4(v[0], v[1], v[2], v[3]);
    __syncthreads();
    #pragma unroll
    for (int s = 128; s >= 1; s >>= 1) {
        if (tid < s) {
            float4 a = red[tid], b = red[tid + s];
            a.x += b.x; a.y += b.y; a.z += b.z; a.w += b.w;
            red[tid] = a;
        }
        __syncthreads();
    }
    float4 r = red[0];
    __syncthreads();
    v[0] = r.x; v[1] = r.y; v[2] = r.z; v[3] = r.w;
}

__global__ __launch_bounds__(256)
void detr3d_fused_kernel(
    const float* __restrict__ query, const float* __restrict__ query_pos,
    const float* __restrict__ refp,  const float* __restrict__ l2i,
    const float* __restrict__ f0, const float* __restrict__ f1,
    const float* __restrict__ f2, const float* __restrict__ f3,
    const float* __restrict__ W_qe,   const float* __restrict__ b_qe,
    const float* __restrict__ W_attn, const float* __restrict__ b_attn,
    const float* __restrict__ W_out,  const float* __restrict__ b_out,
    const float* __restrict__ pe_w1,  const float* __restrict__ pe_b1,
    const float* __restrict__ pe_g1,  const float* __restrict__ pe_be1,
    const float* __restrict__ pe_w2,  const float* __restrict__ pe_b2,
    const float* __restrict__ pe_g2,  const float* __restrict__ pe_be2,
    const float* __restrict__ W_fin,  const float* __restrict__ b_fin,
    const float* __restrict__ g_norm, const float* __restrict__ b_norm,
    float* __restrict__ out)
{
    const int qb  = blockIdx.x * QPB;   // first query of this block
    const int tid = threadIdx.x;

    __shared__ float  sh_q[QPB][64];
    __shared__ float  sh_ref[QPB][3];
    __shared__ float  sh_qe[QPB][256];
    __shared__ float  sh_x[QPB][256];   // gather acc, later h = out+res+pos
    __shared__ float  sh_p[QPB][256];   // pos MLP hidden
    __shared__ float4 sh_red[256];      // reduction scratch (4 KB)
    __shared__ float  sh_w[QPB][24];    // sigmoid(attw)
    __shared__ float  sh_gx[QPB][6], sh_gy[QPB][6];
    __shared__ int    sh_mask[QPB][6];

    // ---- load q = query + query_pos (QPB*64 = 256 values), reference points
    {
        const int j = tid >> 6, c = tid & 63;
        sh_q[j][c] = query[(qb + j) * 64 + c] + query_pos[(qb + j) * 64 + c];
    }
    if (tid < QPB * 3) sh_ref[tid / 3][tid % 3] = refp[(qb + tid / 3) * 3 + tid % 3];
    __syncthreads();

    // ---- qe = q @ W_qe + b_qe (64 -> 256); thread = out channel, 4 queries at once
    float qe[QPB];
    {
        const float b = __ldg(&b_qe[tid]);
        #pragma unroll
        for (int j = 0; j < QPB; j++) qe[j] = b;
        #pragma unroll 8
        for (int k = 0; k < 64; k++) {
            const float w = __ldg(&W_qe[k * 256 + tid]);
            #pragma unroll
            for (int j = 0; j < QPB; j++) qe[j] = fmaf(sh_q[j][k], w, qe[j]);
        }
        #pragma unroll
        for (int j = 0; j < QPB; j++) sh_qe[j][tid] = qe[j];
    }
    __syncthreads();

    // ---- attention weights (threads 0..95) and camera projection (threads 128..151)
    if (tid < QPB * 24) {
        const int j = tid / 24, o = tid % 24;
        float a = __ldg(&b_attn[o]);
        #pragma unroll 2
        for (int k = 0; k < 256; k++)
            a = fmaf(sh_qe[j][k], __ldg(&W_attn[k * 24 + o]), a);
        sh_w[j][o] = 1.0f / (1.0f + expf(-a));
    } else if (tid >= 128 && tid < 128 + QPB * 6) {
        const int idx = tid - 128;
        const int j = idx / 6, n = idx % 6;
        const float* M = l2i + n * 16;
        const float rx = sh_ref[j][0], ry = sh_ref[j][1], rz = sh_ref[j][2];
        float c0 = M[0] * rx + M[1] * ry + M[2]  * rz + M[3];
        float c1 = M[4] * rx + M[5] * ry + M[6]  * rz + M[7];
        float c2 = M[8] * rx + M[9] * ry + M[10] * rz + M[11];
        bool front = c2 > Z_EPS;
        float zc = fmaxf(c2, Z_EPS);
        float gx = (c0 / zc / 1600.0f - 0.5f) * 2.0f;
        float gy = (c1 / zc / 928.0f  - 0.5f) * 2.0f;
        bool inb = (gx > -1.0f) && (gx < 1.0f) && (gy > -1.0f) && (gy < 1.0f);
        sh_gx[j][n] = gx;
        sh_gy[j][n] = gy;
        sh_mask[j][n] = (front && inb) ? 1 : 0;
    }
    __syncthreads();

    // ---- masked bilinear gather, attention-weighted. thread = channel.
    {
        const float* fps[4] = { f0, f1, f2, f3 };
        const int Hs[4] = { 116, 58, 29, 15 };
        const int Ws[4] = { 200, 100, 50, 25 };
        float acc[QPB];
        #pragma unroll
        for (int j = 0; j < QPB; j++) acc[j] = 0.0f;

        #pragma unroll
        for (int j = 0; j < QPB; j++) {
            for (int n = 0; n < 6; n++) {
                if (!sh_mask[j][n]) continue;
                const float gx = sh_gx[j][n], gy = sh_gy[j][n];
                #pragma unroll
                for (int l = 0; l < 4; l++) {
                    const int W = Ws[l], H = Hs[l];
                    const float wnl = sh_w[j][n * 4 + l];
                    float x = ((gx + 1.0f) * (float)W - 1.0f) * 0.5f;
                    float y = ((gy + 1.0f) * (float)H - 1.0f) * 0.5f;
                    float fx0 = floorf(x), fy0 = floorf(y);
                    int x0 = (int)fx0, y0 = (int)fy0;
                    float wx1 = x - fx0, wx0 = 1.0f - wx1;
                    float wy1 = y - fy0, wy0 = 1.0f - wy1;
                    const float* fb = fps[l] + ((size_t)(n * 256 + tid)) * (size_t)(H * W);
                    bool vx0 = (x0 >= 0) && (x0 < W);
                    bool vx1 = (x0 + 1 >= 0) && (x0 + 1 < W);
                    bool vy0 = (y0 >= 0) && (y0 < H);
                    bool vy1 = (y0 + 1 >= 0) && (y0 + 1 < H);
                    float v = 0.0f;
                    if (vy0 && vx0) v = fmaf(wy0 * wx0, __ldg(fb + (size_t)y0 * W + x0), v);
                    if (vy0 && vx1) v = fmaf(wy0 * wx1, __ldg(fb + (size_t)y0 * W + x0 + 1), v);
                    if (vy1 && vx0) v = fmaf(wy1 * wx0, __ldg(fb + (size_t)(y0 + 1) * W + x0), v);
                    if (vy1 && vx1) v = fmaf(wy1 * wx1, __ldg(fb + (size_t)(y0 + 1) * W + x0 + 1), v);
                    acc[j] = fmaf(wnl, v, acc[j]);
                }
            }
        }
        #pragma unroll
        for (int j = 0; j < QPB; j++) sh_x[j][tid] = acc[j];
    }
    __syncthreads();

    // ---- ov = acc @ W_out + b_out (256 -> 256)
    float ov[QPB];
    {
        const float b = __ldg(&b_out[tid]);
        #pragma unroll
        for (int j = 0; j < QPB; j++) ov[j] = b;
        #pragma unroll 2
        for (int k = 0; k < 256; k++) {
            const float w = __ldg(&W_out[k * 256 + tid]);
            #pragma unroll
            for (int j = 0; j < QPB; j++) ov[j] = fmaf(sh_x[j][k], w, ov[j]);
        }
    }

    // ---- positional MLP stage 1: ref @ pe_w1 + pe_b1 -> LN -> relu
    float p[QPB];
    {
        const float w1 = __ldg(&pe_w1[tid]);
        const float w2 = __ldg(&pe_w1[256 + tid]);
        const float w3 = __ldg(&pe_w1[512 + tid]);
        const float b  = __ldg(&pe_b1[tid]);
        #pragma unroll
        for (int j = 0; j < QPB; j++)
            p[j] = b + sh_ref[j][0] * w1 + sh_ref[j][1] * w2 + sh_ref[j][2] * w3;

        float s1[QPB], s2[QPB];
        #pragma unroll
        for (int j = 0; j < QPB; j++) { s1[j] = p[j]; }
        blockSum256x4(s1, sh_red);
        #pragma unroll
        for (int j = 0; j < QPB; j++) { s2[j] = p[j] * p[j]; }
        blockSum256x4(s2, sh_red);

        const float g = __ldg(&pe_g1[tid]), be = __ldg(&pe_be1[tid]);
        #pragma unroll
        for (int j = 0; j < QPB; j++) {
            float m = s1[j] * (1.0f / 256.0f);
            float var = s2[j] * (1.0f / 256.0f) - m * m;
            float val = (p[j] - m) * rsqrtf(var + LN_EPS) * g + be;
            sh_p[j][tid] = fmaxf(val, 0.0f);
        }
    }
    __syncthreads();

    // ---- positional MLP stage 2: @ pe_w2 + pe_b2 -> LN -> relu
    float p2[QPB];
    {
        const float b = __ldg(&pe_b2[tid]);
        #pragma unroll
        for (int j = 0; j < QPB; j++) p2[j] = b;
        #pragma unroll 2
        for (int k = 0; k < 256; k++) {
            const float w = __ldg(&pe_w2[k * 256 + tid]);
            #pragma unroll
            for (int j = 0; j < QPB; j++) p2[j] = fmaf(sh_p[j][k], w, p2[j]);
        }
        float s1[QPB], s2[QPB];
        #pragma unroll
        for (int j = 0; j < QPB; j++) { s1[j] = p2[j]; }
        blockSum256x4(s1, sh_red);
        #pragma unroll
        for (int j = 0; j < QPB; j++) { s2[j] = p2[j] * p2[j]; }
        blockSum256x4(s2, sh_red);

        const float g = __ldg(&pe_g2[tid]), be = __ldg(&pe_be2[tid]);
        #pragma unroll
        for (int j = 0; j < QPB; j++) {
            float m = s1[j] * (1.0f / 256.0f);
            float var = s2[j] * (1.0f / 256.0f) - m * m;
            float val = (p2[j] - m) * rsqrtf(var + LN_EPS) * g + be;
            p2[j] = fmaxf(val, 0.0f);
        }
    }

    // ---- h = ov + residual(qe) + pos
    #pragma unroll
    for (int j = 0; j < QPB; j++) sh_x[j][tid] = ov[j] + qe[j] + p2[j];
    __syncthreads();

    // ---- final: y = h @ W_fin + b_fin (256 -> 64), then LayerNorm over 64.
    // Remap: tid -> (query j2 = tid>>6, channel c = tid&63); all 256 threads active.
    {
        const int j2 = tid >> 6, c = tid & 63;
        float y = __ldg(&b_fin[c]);
        #pragma unroll 2
        for (int k = 0; k < 256; k++)
            y = fmaf(sh_x[j2][k], __ldg(&W_fin[k * 64 + c]), y);

        float* r1 = (float*)sh_red;        // 1024 floats available
        float* r2 = r1 + 256;
        r1[tid] = y;
        r2[tid] = y * y;
        __syncthreads();
        #pragma unroll
        for (int s = 32; s >= 1; s >>= 1) {
            if ((tid & 63) < s) { r1[tid] += r1[tid + s]; r2[tid] += r2[tid + s]; }
            __syncthreads();
        }
        const int seg = tid & ~63;
        float m   = r1[seg] * (1.0f / 64.0f);
        float var = r2[seg] * (1.0f / 64.0f) - m * m;
        out[(qb + j2) * 64 + c] =
            (y - m) * rsqrtf(var + LN_EPS) * __ldg(&g_norm[c]) + __ldg(&b_norm[c]);
    }
}

extern "C" void kernel_launch(void* const* d_in, const int* in_sizes, int n_in,
                              void* d_out, int out_size) {
    (void)in_sizes; (void)n_in; (void)out_size;
    const float* query     = (const float*)d_in[0];
    const float* query_pos = (const float*)d_in[1];
    const float* refp      = (const float*)d_in[2];
    const float* l2i       = (const float*)d_in[3];
    const float* f0        = (const float*)d_in[4];
    const float* f1        = (const float*)d_in[5];
    const float* f2        = (const float*)d_in[6];
    const float* f3        = (const float*)d_in[7];
    const float* W_qe      = (const float*)d_in[8];
    const float* b_qe      = (const float*)d_in[9];
    const float* W_attn    = (const float*)d_in[10];
    const float* b_attn    = (const float*)d_in[11];
    const float* W_out     = (const float*)d_in[12];
    const float* b_out     = (const float*)d_in[13];
    const float* pe_w1     = (const float*)d_in[14];
    const float* pe_b1     = (const float*)d_in[15];
    const float* pe_g1     = (const float*)d_in[16];
    const float* pe_be1    = (const float*)d_in[17];
    const float* pe_w2     = (const float*)d_in[18];
    const float* pe_b2     = (const float*)d_in[19];
    const float* pe_g2     = (const float*)d_in[20];
    const float* pe_be2    = (const float*)d_in[21];
    const float* W_fin     = (const float*)d_in[22];
    const float* b_fin     = (const float*)d_in[23];
    const float* g_norm    = (const float*)d_in[24];
    const float* b_norm    = (const float*)d_in[25];

    detr3d_fused_kernel<<<1024 / QPB, 256>>>(
        query, query_pos, refp, l2i, f0, f1, f2, f3,
        W_qe, b_qe, W_attn, b_attn, W_out, b_out,
        pe_w1, pe_b1, pe_g1, pe_be1, pe_w2, pe_b2, pe_g2, pe_be2,
        W_fin, b_fin, g_norm, b_norm, (float*)d_out);
}

// round 4
// speedup vs baseline: 2.2486x; 2.2486x over previous
#include <cuda_runtime.h>

#define QPB 2          // queries per block
#define LN_EPS 1e-5f
#define Z_EPS  1e-5f

// Block-wide sum of a float4 across 256 threads (3 barriers).
// Used to reduce (s1_q0, s1_q1, s2_q0, s2_q1) in one pass.
__device__ __forceinline__ float4 blockSum4(float4 v, float4* red) {
    const int tid  = threadIdx.x;
    const int lane = tid & 31, warp = tid >> 5;
    #pragma unroll
    for (int s = 16; s >= 1; s >>= 1) {
        v.x += __shfl_xor_sync(0xffffffffu, v.x, s);
        v.y += __shfl_xor_sync(0xffffffffu, v.y, s);
        v.z += __shfl_xor_sync(0xffffffffu, v.z, s);
        v.w += __shfl_xor_sync(0xffffffffu, v.w, s);
    }
    if (lane == 0) red[warp] = v;
    __syncthreads();
    if (warp == 0) {
        float4 t = (lane < 8) ? red[lane] : make_float4(0.f, 0.f, 0.f, 0.f);
        #pragma unroll
        for (int s = 4; s >= 1; s >>= 1) {
            t.x += __shfl_xor_sync(0xffffffffu, t.x, s);
            t.y += __shfl_xor_sync(0xffffffffu, t.y, s);
            t.z += __shfl_xor_sync(0xffffffffu, t.z, s);
            t.w += __shfl_xor_sync(0xffffffffu, t.w, s);
        }
        if (lane == 0) red[0] = t;
    }
    __syncthreads();
    float4 r = red[0];
    __syncthreads();
    return r;
}

__global__ __launch_bounds__(256)
void detr3d_fused_kernel(
    const float* __restrict__ query, const float* __restrict__ query_pos,
    const float* __restrict__ refp,  const float* __restrict__ l2i,
    const float* __restrict__ f0, const float* __restrict__ f1,
    const float* __restrict__ f2, const float* __restrict__ f3,
    const float* __restrict__ W_qe,   const float* __restrict__ b_qe,
    const float* __restrict__ W_attn, const float* __restrict__ b_attn,
    const float* __restrict__ W_out,  const float* __restrict__ b_out,
    const float* __restrict__ pe_w1,  const float* __restrict__ pe_b1,
    const float* __restrict__ pe_g1,  const float* __restrict__ pe_be1,
    const float* __restrict__ pe_w2,  const float* __restrict__ pe_b2,
    const float* __restrict__ pe_g2,  const float* __restrict__ pe_be2,
    const float* __restrict__ W_fin,  const float* __restrict__ b_fin,
    const float* __restrict__ g_norm, const float* __restrict__ b_norm,
    float* __restrict__ out)
{
    const int qb   = blockIdx.x * QPB;
    const int tid  = threadIdx.x;
    const int lane = tid & 31, warp = tid >> 5;

    __shared__ float  sh_q[QPB][64];
    __shared__ float  sh_ref[QPB][3];
    __shared__ float  sh_qe[QPB][256];
    __shared__ float  sh_x[QPB][256];    // gather acc; later h = out+res+pos
    __shared__ float  sh_p[QPB][256];    // pos MLP hidden; later W_fin scratch
    __shared__ float4 sh_red[8];
    __shared__ float2 sh_fin[8];
    __shared__ float  sh_w[QPB][24];     // sigmoid(attw)
    __shared__ float  sh_gx[QPB][6], sh_gy[QPB][6];
    __shared__ int    sh_mask[QPB][6];

    // ---- load q = query + query_pos (QPB*64 = 128 values), reference points
    if (tid < QPB * 64) {
        const int j = tid >> 6, c = tid & 63;
        sh_q[j][c] = query[(qb + j) * 64 + c] + query_pos[(qb + j) * 64 + c];
    }
    if (tid >= 128 && tid < 128 + QPB * 3) {
        const int i = tid - 128;
        sh_ref[i / 3][i % 3] = refp[(qb + i / 3) * 3 + i % 3];
    }
    __syncthreads();

    // ---- qe = q @ W_qe + b_qe (64 -> 256); thread = out channel
    float qe[QPB];
    {
        const float b = __ldg(&b_qe[tid]);
        #pragma unroll
        for (int j = 0; j < QPB; j++) qe[j] = b;
        #pragma unroll 8
        for (int k = 0; k < 64; k++) {
            const float w = __ldg(&W_qe[k * 256 + tid]);
            #pragma unroll
            for (int j = 0; j < QPB; j++) qe[j] = fmaf(sh_q[j][k], w, qe[j]);
        }
        #pragma unroll
        for (int j = 0; j < QPB; j++) sh_qe[j][tid] = qe[j];
    }
    // ---- camera projection (threads 0..11), same stage
    if (tid < QPB * 6) {
        const int j = tid / 6, n = tid % 6;
        const float* M = l2i + n * 16;
        const float rx = sh_ref[j][0], ry = sh_ref[j][1], rz = sh_ref[j][2];
        float c0 = M[0] * rx + M[1] * ry + M[2]  * rz + M[3];
        float c1 = M[4] * rx + M[5] * ry + M[6]  * rz + M[7];
        float c2 = M[8] * rx + M[9] * ry + M[10] * rz + M[11];
        bool front = c2 > Z_EPS;
        float zc = fmaxf(c2, Z_EPS);
        float gx = (c0 / zc / 1600.0f - 0.5f) * 2.0f;
        float gy = (c1 / zc / 928.0f  - 0.5f) * 2.0f;
        bool inb = (gx > -1.0f) && (gx < 1.0f) && (gy > -1.0f) && (gy < 1.0f);
        sh_gx[j][n] = gx;
        sh_gy[j][n] = gy;
        sh_mask[j][n] = (front && inb) ? 1 : 0;
    }
    __syncthreads();

    // ---- attw: warp-split GEMV. warp w owns outputs {w, w+8, w+16};
    //      lanes split k (8 iters each), shuffle-reduce, lane 0 writes sigmoid.
    {
        float acc[3][QPB];
        #pragma unroll
        for (int i = 0; i < 3; i++)
            #pragma unroll
            for (int j = 0; j < QPB; j++) acc[i][j] = 0.0f;
        #pragma unroll
        for (int kk = 0; kk < 8; kk++) {
            const int k = lane + 32 * kk;
            const float q0 = sh_qe[0][k];
            const float q1 = sh_qe[1][k];
            #pragma unroll
            for (int i = 0; i < 3; i++) {
                const float wv = __ldg(&W_attn[k * 24 + warp + 8 * i]);
                acc[i][0] = fmaf(q0, wv, acc[i][0]);
                acc[i][1] = fmaf(q1, wv, acc[i][1]);
            }
        }
        #pragma unroll
        for (int i = 0; i < 3; i++)
            #pragma unroll
            for (int j = 0; j < QPB; j++) {
                #pragma unroll
                for (int s = 16; s >= 1; s >>= 1)
                    acc[i][j] += __shfl_xor_sync(0xffffffffu, acc[i][j], s);
            }
        if (lane == 0) {
            #pragma unroll
            for (int i = 0; i < 3; i++) {
                const int o = warp + 8 * i;
                const float b = __ldg(&b_attn[o]);
                #pragma unroll
                for (int j = 0; j < QPB; j++)
                    sh_w[j][o] = 1.0f / (1.0f + expf(-(acc[i][j] + b)));
            }
        }
    }
    __syncthreads();

    // ---- masked bilinear gather, attention-weighted. thread = channel.
    {
        const float* fps[4] = { f0, f1, f2, f3 };
        const int Hs[4] = { 116, 58, 29, 15 };
        const int Ws[4] = { 200, 100, 50, 25 };
        float acc[QPB];
        #pragma unroll
        for (int j = 0; j < QPB; j++) acc[j] = 0.0f;

        #pragma unroll
        for (int j = 0; j < QPB; j++) {
            for (int n = 0; n < 6; n++) {
                if (!sh_mask[j][n]) continue;
                const float gx = sh_gx[j][n], gy = sh_gy[j][n];
                #pragma unroll
                for (int l = 0; l < 4; l++) {
                    const int W = Ws[l], H = Hs[l];
                    const float wnl = sh_w[j][n * 4 + l];
                    float x = ((gx + 1.0f) * (float)W - 1.0f) * 0.5f;
                    float y = ((gy + 1.0f) * (float)H - 1.0f) * 0.5f;
                    float fx0 = floorf(x), fy0 = floorf(y);
                    int x0 = (int)fx0, y0 = (int)fy0;
                    float wx1 = x - fx0, wx0 = 1.0f - wx1;
                    float wy1 = y - fy0, wy0 = 1.0f - wy1;
                    const float* fb = fps[l] + ((size_t)(n * 256 + tid)) * (size_t)(H * W);
                    bool vx0 = (x0 >= 0) && (x0 < W);
                    bool vx1 = (x0 + 1 >= 0) && (x0 + 1 < W);
                    bool vy0 = (y0 >= 0) && (y0 < H);
                    bool vy1 = (y0 + 1 >= 0) && (y0 + 1 < H);
                    float v = 0.0f;
                    if (vy0 && vx0) v = fmaf(wy0 * wx0, __ldg(fb + (size_t)y0 * W + x0), v);
                    if (vy0 && vx1) v = fmaf(wy0 * wx1, __ldg(fb + (size_t)y0 * W + x0 + 1), v);
                    if (vy1 && vx0) v = fmaf(wy1 * wx0, __ldg(fb + (size_t)(y0 + 1) * W + x0), v);
                    if (vy1 && vx1) v = fmaf(wy1 * wx1, __ldg(fb + (size_t)(y0 + 1) * W + x0 + 1), v);
                    acc[j] = fmaf(wnl, v, acc[j]);
                }
            }
        }
        #pragma unroll
        for (int j = 0; j < QPB; j++) sh_x[j][tid] = acc[j];
    }
    __syncthreads();

    // ---- ov = acc @ W_out + b_out (256 -> 256)
    float ov[QPB];
    {
        const float b = __ldg(&b_out[tid]);
        #pragma unroll
        for (int j = 0; j < QPB; j++) ov[j] = b;
        #pragma unroll 8
        for (int k = 0; k < 256; k++) {
            const float w = __ldg(&W_out[k * 256 + tid]);
            #pragma unroll
            for (int j = 0; j < QPB; j++) ov[j] = fmaf(sh_x[j][k], w, ov[j]);
        }
    }

    // ---- positional MLP stage 1: ref @ pe_w1 + pe_b1 -> LN -> relu
    {
        const float w1 = __ldg(&pe_w1[tid]);
        const float w2 = __ldg(&pe_w1[256 + tid]);
        const float w3 = __ldg(&pe_w1[512 + tid]);
        const float b  = __ldg(&pe_b1[tid]);
        float p[QPB];
        #pragma unroll
        for (int j = 0; j < QPB; j++)
            p[j] = b + sh_ref[j][0] * w1 + sh_ref[j][1] * w2 + sh_ref[j][2] * w3;

        float4 s = blockSum4(make_float4(p[0], p[1], p[0]*p[0], p[1]*p[1]), sh_red);
        const float g = __ldg(&pe_g1[tid]), be = __ldg(&pe_be1[tid]);
        {
            float m = s.x * (1.0f / 256.0f);
            float var = s.z * (1.0f / 256.0f) - m * m;
            sh_p[0][tid] = fmaxf((p[0] - m) * rsqrtf(var + LN_EPS) * g + be, 0.0f);
        }
        {
            float m = s.y * (1.0f / 256.0f);
            float var = s.w * (1.0f / 256.0f) - m * m;
            sh_p[1][tid] = fmaxf((p[1] - m) * rsqrtf(var + LN_EPS) * g + be, 0.0f);
        }
    }
    __syncthreads();

    // ---- positional MLP stage 2: @ pe_w2 + pe_b2 -> LN -> relu
    float p2[QPB];
    {
        const float b = __ldg(&pe_b2[tid]);
        #pragma unroll
        for (int j = 0; j < QPB; j++) p2[j] = b;
        #pragma unroll 8
        for (int k = 0; k < 256; k++) {
            const float w = __ldg(&pe_w2[k * 256 + tid]);
            #pragma unroll
            for (int j = 0; j < QPB; j++) p2[j] = fmaf(sh_p[j][k], w, p2[j]);
        }
        float4 s = blockSum4(make_float4(p2[0], p2[1], p2[0]*p2[0], p2[1]*p2[1]), sh_red);
        const float g = __ldg(&pe_g2[tid]), be = __ldg(&pe_be2[tid]);
        {
            float m = s.x * (1.0f / 256.0f);
            float var = s.z * (1.0f / 256.0f) - m * m;
            p2[0] = fmaxf((p2[0] - m) * rsqrtf(var + LN_EPS) * g + be, 0.0f);
        }
        {
            float m = s.y * (1.0f / 256.0f);
            float var = s.w * (1.0f / 256.0f) - m * m;
            p2[1] = fmaxf((p2[1] - m) * rsqrtf(var + LN_EPS) * g + be, 0.0f);
        }
    }

    // ---- h = ov + residual(qe) + pos
    #pragma unroll
    for (int j = 0; j < QPB; j++) sh_x[j][tid] = ov[j] + qe[j] + p2[j];
    __syncthreads();

    // ---- final: y = h @ W_fin + b_fin (256 -> 64), split-k over 2 parts, then LN(64).
    {
        const int j2   = tid >> 7;          // query within block
        const int rem  = tid & 127;
        const int part = rem >> 6;          // k-half
        const int c    = rem & 63;          // output channel
        float y = (part == 0) ? __ldg(&b_fin[c]) : 0.0f;
        const int k0 = part * 128;
        #pragma unroll 8
        for (int k = k0; k < k0 + 128; k++)
            y = fmaf(sh_x[j2][k], __ldg(&W_fin[k * 64 + c]), y);

        float* r1 = &sh_p[0][0];            // reuse 512 floats of sh_p
        r1[tid] = y;
        __syncthreads();

        float y2 = 0.0f;
        if (part == 0) y2 = r1[tid] + r1[tid + 64];

        // LN sums over the 64 channels of each query: warp butterfly + 2-warp combine
        float sx = y2, sxx = y2 * y2;
        #pragma unroll
        for (int s = 16; s >= 1; s >>= 1) {
            sx  += __shfl_xor_sync(0xffffffffu, sx,  s);
            sxx += __shfl_xor_sync(0xffffffffu, sxx, s);
        }
        if (lane == 0) sh_fin[warp] = make_float2(sx, sxx);
        __syncthreads();

        if (part == 0) {
            float2 a = sh_fin[j2 * 4];
            float2 b = sh_fin[j2 * 4 + 1];
            float m   = (a.x + b.x) * (1.0f / 64.0f);
            float var = (a.y + b.y) * (1.0f / 64.0f) - m * m;
            out[(qb + j2) * 64 + c] =
                (y2 - m) * rsqrtf(var + LN_EPS) * __ldg(&g_norm[c]) + __ldg(&b_norm[c]);
        }
    }
}

extern "C" void kernel_launch(void* const* d_in, const int* in_sizes, int n_in,
                              void* d_out, int out_size) {
    (void)in_sizes; (void)n_in; (void)out_size;
    const float* query     = (const float*)d_in[0];
    const float* query_pos = (const float*)d_in[1];
    const float* refp      = (const float*)d_in[2];
    const float* l2i       = (const float*)d_in[3];
    const float* f0        = (const float*)d_in[4];
    const float* f1        = (const float*)d_in[5];
    const float* f2        = (const float*)d_in[6];
    const float* f3        = (const float*)d_in[7];
    const float* W_qe      = (const float*)d_in[8];
    const float* b_qe      = (const float*)d_in[9];
    const float* W_attn    = (const float*)d_in[10];
    const float* b_attn    = (const float*)d_in[11];
    const float* W_out     = (const float*)d_in[12];
    const float* b_out     = (const float*)d_in[13];
    const float* pe_w1     = (const float*)d_in[14];
    const float* pe_b1     = (const float*)d_in[15];
    const float* pe_g1     = (const float*)d_in[16];
    const float* pe_be1    = (const float*)d_in[17];
    const float* pe_w2     = (const float*)d_in[18];
    const float* pe_b2     = (const float*)d_in[19];
    const float* pe_g2     = (const float*)d_in[20];
    const float* pe_be2    = (const float*)d_in[21];
    const float* W_fin     = (const float*)d_in[22];
    const float* b_fin     = (const float*)d_in[23];
    const float* g_norm    = (const float*)d_in[24];
    const float* b_norm    = (const float*)d_in[25];

    detr3d_fused_kernel<<<1024 / QPB, 256>>>(
        query, query_pos, refp, l2i, f0, f1, f2, f3,
        W_qe, b_qe, W_attn, b_attn, W_out, b_out,
        pe_w1, pe_b1, pe_g1, pe_be1, pe_w2, pe_b2, pe_g2, pe_be2,
        W_fin, b_fin, g_norm, b_norm, (float*)d_out);
}